// round 1
// baseline (speedup 1.0000x reference)
#include <cuda_runtime.h>

// Problem constants (fixed by the reference)
#define BB 32
#define TT 256
#define NN 1536
#define NI 768

// Kernel config: one thread owns NPT=2 neurons for one batch.
#define NPT 2
#define GROUPS (NN / NPT)          // 768 groups per batch
#define TPB 192
#define NBLK ((BB * GROUPS) / TPB) // 128 blocks (<= SM count -> co-resident)

// exp constants, correctly rounded fp32
#define AR0 0.13533528323661270f   // exp(-2)    : rise tau 0.5 (syn0, syn2, FF)
#define AR1 0.60653065971263342f   // exp(-0.5)  : rise tau 2   (syn1)
#define AD0 0.60653065971263342f   // exp(-0.5)  : decay tau 2  (syn0, FF)
#define AD1 0.99004983374916805f   // exp(-0.01) : decay tau 100(syn1)
#define AD2 0.81873075307798186f   // exp(-0.2)  : decay tau 5  (syn2)

// ------------------------- device scratch (statics; no allocs) -------------
__device__ float d_Wsc[NN * NN];        // weights * sf[ct[n]][ct[m]]
__device__ float d_WFsc[NI * NN];       // weights_FF * sfF[ct[m]]
__device__ int   d_list[3][BB][NN];     // tri-buffered spike lists: n | (ct<<16)
__device__ int   d_cnt[3][BB];
__device__ int   d_ffcnt[BB * TT];      // input spike lists per (b,t)
__device__ int   d_fflist[BB * TT][NI];
__device__ unsigned d_arrive;           // grid barrier counter

// ------------------------- init ---------------------------------------------
__global__ void init_k() {
    int i = threadIdx.x;
    if (i < 3 * BB) ((int*)d_cnt)[i] = 0;
    if (i == 3 * BB) d_arrive = 0u;
}

// ------------------------- weight scaling ----------------------------------
__global__ void scale_k(const float* __restrict__ w, const float* __restrict__ wff,
                        const float* __restrict__ sf, const float* __restrict__ sff,
                        const int* __restrict__ ct) {
    int idx = blockIdx.x * 256 + threadIdx.x;
    if (idx < NN * NN) {
        int n = idx / NN, m = idx % NN;
        d_Wsc[idx] = w[idx] * sf[ct[n] * 2 + ct[m]];
    } else {
        int r = idx - NN * NN;
        if (r < NI * NN) {
            int m = r % NN;
            d_WFsc[r] = wff[r] * sff[ct[m]];   // ct_FF is all zeros -> row 0
        }
    }
}

// ------------------------- FF spike lists ----------------------------------
__global__ void ffl_k(const float* __restrict__ inp) {
    int bt = blockIdx.x;                      // bt = b*TT + t
    __shared__ int scnt;
    __shared__ int sl[NI];
    if (threadIdx.x == 0) scnt = 0;
    __syncthreads();
    const float* row = inp + (size_t)bt * NI;
    for (int i = threadIdx.x; i < NI; i += blockDim.x)
        if (row[i] > 0.5f) { int p = atomicAdd(&scnt, 1); sl[p] = i; }
    __syncthreads();
    int c = scnt;
    if (threadIdx.x == 0) d_ffcnt[bt] = c;
    for (int e = threadIdx.x; e < c; e += blockDim.x) d_fflist[bt][e] = sl[e];
}

// ------------------------- main persistent simulator ------------------------
__global__ void __launch_bounds__(TPB, 1)
sim_k(const int* __restrict__ ct, float* __restrict__ out) {
    const int gt  = blockIdx.x * TPB + threadIdx.x;
    const int b   = gt / GROUPS;
    const int nq  = gt % GROUPS;
    const int n0  = nq * NPT;
    const int tid = threadIdx.x;

    __shared__ int s_cnt, s_fc;
    __shared__ int s_list[NN];
    __shared__ int s_ff[NI];

    // per-neuron parameters (only leak_coef and ref_steps differ by type)
    float leak[NPT], refstep[NPT];
    int ctk[NPT];
#pragma unroll
    for (int k = 0; k < NPT; k++) {
        int c = ct[n0 + k];
        ctk[k] = c;
        leak[k]    = c ? 0.01f : 0.005f;   // DT/(tau_mem*g_l)
        refstep[k] = c ? 1.0f : 2.0f;      // tau_ref/DT
    }

    float U[NPT], x0[NPT], x1[NPT], x2[NPT], g0[NPT], g1[NPT], g2[NPT],
          xF[NPT], gF[NPT], ref[NPT];
#pragma unroll
    for (int k = 0; k < NPT; k++) {
        U[k] = -65.0f;
        x0[k] = x1[k] = x2[k] = g0[k] = g1[k] = g2[k] = xF[k] = gF[k] = ref[k] = 0.0f;
    }

    const float* Wb  = d_Wsc  + n0;
    const float* WFb = d_WFsc + n0;
    const size_t VOFF = (size_t)BB * TT * NN;

    for (int t = 0; t < TT; t++) {
        const int prev = (t + 2) % 3, cur = t % 3, nxt = (t + 1) % 3;

        if (tid == 0) {
            s_cnt = __ldcg(&d_cnt[prev][b]);
            s_fc  = d_ffcnt[b * TT + t];
        }
        __syncthreads();
        int cnt = s_cnt; if (cnt > NN) cnt = NN;
        int fc  = s_fc;  if (fc  > NI) fc  = NI;

        // stage spike lists into smem (cooperative, L1-bypassing for rec list)
        for (int e = tid; e < cnt; e += TPB) s_list[e] = __ldcg(&d_list[prev][b][e]);
        for (int e = tid; e < fc;  e += TPB) s_ff[e]   = d_fflist[b * TT + t][e];
        // reset the count of the buffer that will be written at t+1
        // (it was last read at t-1; all reads completed at that barrier)
        if (nq == 0) d_cnt[nxt][b] = 0;
        __syncthreads();

        // -------- sparse gather: recurrent (split by presyn cell type) -----
        float aA0 = 0.f, aA1 = 0.f, aB0 = 0.f, aB1 = 0.f, aF0 = 0.f, aF1 = 0.f;
#pragma unroll 8
        for (int e = 0; e < cnt; e++) {
            int en = s_list[e];
            const float2 w = *(const float2*)(Wb + (en & 0xFFFF) * NN);
            if (en & 0x10000) { aB0 += w.x; aB1 += w.y; }
            else              { aA0 += w.x; aA1 += w.y; }
        }
        // -------- sparse gather: feed-forward ------------------------------
#pragma unroll 8
        for (int e = 0; e < fc; e++) {
            const float2 w = *(const float2*)(WFb + s_ff[e] * NN);
            aF0 += w.x; aF1 += w.y;
        }

        float inA[NPT] = {aA0, aA1};
        float inB[NPT] = {aB0, aB1};
        float inF[NPT] = {aF0, aF1};
        float spkv[NPT], uv[NPT];

#pragma unroll
        for (int k = 0; k < NPT; k++) {
            x0[k] = AR0 * x0[k] + inA[k];
            x1[k] = AR1 * x1[k] + inA[k];
            x2[k] = AR0 * x2[k] + inB[k];
            g0[k] = AD0 * g0[k] + x0[k];
            g1[k] = AD1 * g1[k] + x1[k];
            g2[k] = AD2 * g2[k] + x2[k];
            xF[k] = AR0 * xF[k] + inF[k];
            gF[k] = AD0 * gF[k] + xF[k];

            float gtot = g0[k] + 0.5f * g1[k] + g2[k] + gF[k];
            float gE   = -70.0f * g2[k];
            float Isyn = gE - gtot * U[k];
            float Un   = U[k] + leak[k] * (10.0f * (-65.0f - U[k]) + Isyn);
            if (ref[k] > 0.0f) Un = -65.0f;          // refractory clamp
            ref[k] = fmaxf(ref[k] - 1.0f, 0.0f);
            float s = ((Un - (-50.0f)) >= 0.0f) ? 1.0f : 0.0f;
            if (s > 0.0f) { Un = -65.0f; ref[k] = refstep[k]; }
            U[k] = Un;
            spkv[k] = s;
            uv[k]   = Un;
        }

        // outputs: spikes then volts, both (B,T,N)
        size_t o = ((size_t)b * TT + t) * NN + n0;
        *(float2*)(out + o)        = make_float2(spkv[0], spkv[1]);
        *(float2*)(out + VOFF + o) = make_float2(uv[0], uv[1]);

        // append spikes to current buffer
#pragma unroll
        for (int k = 0; k < NPT; k++) {
            if (spkv[k] > 0.0f) {
                int p = atomicAdd(&d_cnt[cur][b], 1);
                d_list[cur][b][p] = (n0 + k) | (ctk[k] << 16);
            }
        }

        // -------- grid barrier (monotonic counter; CG-style fencing) -------
        __syncthreads();
        if (tid == 0) {
            __threadfence();
            atomicAdd(&d_arrive, 1u);
            unsigned tgt = (unsigned)(t + 1) * (unsigned)gridDim.x;
            while (*(volatile unsigned*)&d_arrive < tgt) { __nanosleep(64); }
            __threadfence();
        }
        __syncthreads();
    }
}

// ------------------------- launcher -----------------------------------------
extern "C" void kernel_launch(void* const* d_in, const int* in_sizes, int n_in,
                              void* d_out, int out_size) {
    const float* input_spikes = (const float*)d_in[0]; // (B,T,NI)
    const float* weights      = (const float*)d_in[1]; // (NN,NN)
    const float* weights_FF   = (const float*)d_in[2]; // (NI,NN)
    const float* sf           = (const float*)d_in[3]; // (2,2)
    const float* sff          = (const float*)d_in[4]; // (1,2)
    const int*   ct           = (const int*)d_in[5];   // (NN,)
    (void)d_in[6]; (void)in_sizes; (void)n_in; (void)out_size;

    init_k<<<1, 128>>>();
    int total = NN * NN + NI * NN;
    scale_k<<<(total + 255) / 256, 256>>>(weights, weights_FF, sf, sff, ct);
    ffl_k<<<BB * TT, 256>>>(input_spikes);
    sim_k<<<NBLK, TPB>>>(ct, (float*)d_out);
}

// round 2
// speedup vs baseline: 1.1446x; 1.1446x over previous
#include <cuda_runtime.h>

// Problem constants (fixed by the reference)
#define BB 32
#define TT 256
#define NN 1536
#define NI 768

// Sim config: 4 CTAs per batch, 384 threads each, 1 neuron per thread.
#define GC   4
#define TPB2 384
#define NWARP (TPB2 / 32)

// exp constants, correctly rounded fp32
#define AR0 0.13533528323661270f   // exp(-2)    : rise tau 0.5 (syn0, syn2, FF)
#define AR1 0.60653065971263342f   // exp(-0.5)  : rise tau 2   (syn1)
#define AD0 0.60653065971263342f   // exp(-0.5)  : decay tau 2  (syn0, FF)
#define AD1 0.99004983374916805f   // exp(-0.01) : decay tau 100(syn1)
#define AD2 0.81873075307798186f   // exp(-0.2)  : decay tau 5  (syn2)

// ------------------------- device scratch (statics; no allocs) -------------
__device__ float d_Wsc[NN * NN];          // weights * sf[ct[n]][ct[m]]
__device__ float d_WFsc[NI * NN];         // weights_FF * sfF[ct[m]]
__device__ float d_IF[(size_t)BB * TT * NN]; // precomputed FF drive (50 MB)
__device__ int   d_ffcnt[BB * TT];        // input spike lists per (b,t)
__device__ int   d_fflist[BB * TT][NI];
__device__ int   d_seg[BB][2][GC][TPB2];  // per-CTA spike segments (dbl buffered)
__device__ int   d_segcnt[BB][2][GC];
__device__ unsigned d_bar[BB];            // per-batch barrier counters

// ------------------------- init ---------------------------------------------
__global__ void init_k() {
    int i = threadIdx.x;
    if (i < BB) d_bar[i] = 0u;
}

// ------------------------- weight scaling ----------------------------------
__global__ void scale_k(const float* __restrict__ w, const float* __restrict__ wff,
                        const float* __restrict__ sf, const float* __restrict__ sff,
                        const int* __restrict__ ct) {
    int idx = blockIdx.x * 256 + threadIdx.x;
    if (idx < NN * NN) {
        int n = idx / NN, m = idx % NN;
        d_Wsc[idx] = w[idx] * sf[ct[n] * 2 + ct[m]];
    } else {
        int r = idx - NN * NN;
        if (r < NI * NN) {
            int m = r % NN;
            d_WFsc[r] = wff[r] * sff[ct[m]];   // ct_FF is all zeros -> row 0
        }
    }
}

// ------------------------- FF spike lists (ballot-ordered, deterministic) --
__global__ void ffl_k(const float* __restrict__ inp) {
    int bt = blockIdx.x;                      // bt = b*TT + t
    int lane = threadIdx.x;
    const float* row = inp + (size_t)bt * NI;
    int cnt = 0;
    for (int base = 0; base < NI; base += 32) {
        float v = row[base + lane];
        unsigned m = __ballot_sync(0xFFFFFFFFu, v > 0.5f);
        if (v > 0.5f) {
            int p = cnt + __popc(m & ((1u << lane) - 1u));
            d_fflist[bt][p] = base + lane;
        }
        cnt += __popc(m);
    }
    if (lane == 0) d_ffcnt[bt] = cnt;
}

// ------------------------- FF drive precompute ------------------------------
// CTA = (32-col tile, batch). Warp w handles t = p*32 + w; lanes span columns.
// The 768x32-col fp32 slab (98 KB) stays L1-resident -> L1-wavefront bound.
#define FTPB 1024
__global__ void __launch_bounds__(FTPB, 1) ffpre_k() {
    int b  = blockIdx.y;
    int c0 = blockIdx.x * 32;
    int w    = threadIdx.x >> 5;
    int lane = threadIdx.x & 31;
    const float* __restrict__ Wc = d_WFsc + c0 + lane;
#pragma unroll
    for (int p = 0; p < TT / 32; p++) {
        int t  = p * 32 + w;
        int bt = b * TT + t;
        int fc = d_ffcnt[bt];
        float acc0 = 0.f, acc1 = 0.f;
        const int* __restrict__ lst = d_fflist[bt];
#pragma unroll 8
        for (int e = 0; e < fc; e++) {
            float v = Wc[lst[e] * NN];
            if (e & 1) acc1 += v; else acc0 += v;
        }
        d_IF[(size_t)bt * NN + c0 + lane] = acc0 + acc1;
    }
}

// ------------------------- main persistent simulator ------------------------
__global__ void __launch_bounds__(TPB2, 1)
sim_k(const int* __restrict__ ct, float* __restrict__ out) {
    const int b    = blockIdx.x / GC;
    const int rank = blockIdx.x % GC;
    const int tid  = threadIdx.x;
    const int wid  = tid >> 5, lane = tid & 31;
    const int n    = rank * TPB2 + tid;

    __shared__ int s_list[NN];
    __shared__ int s_wcnt[NWARP];

    const int   c       = ct[n];
    const float leak    = c ? 0.01f : 0.005f;   // DT/(tau_mem*g_l)
    const float refstep = c ? 1.0f : 2.0f;      // tau_ref/DT

    float U = -65.0f, x0 = 0, x1 = 0, x2 = 0, g0 = 0, g1 = 0, g2 = 0,
          xF = 0, gF = 0, ref = 0;

    const float* __restrict__ Wcol = d_Wsc + n;
    const size_t VOFF = (size_t)BB * TT * NN;
    int cnt = 0;                                 // combined spike count (t-1)

    for (int t = 0; t < TT; t++) {
        const int par = t & 1;

        // FF drive (precomputed), issued early to overlap with gather
        float inF = __ldcg(&d_IF[((size_t)b * TT + t) * NN + n]);

        // -------- sparse recurrent gather (split by presyn cell type) ------
        float aA0 = 0.f, aA1 = 0.f, aB0 = 0.f, aB1 = 0.f;
#pragma unroll 16
        for (int e = 0; e < cnt; e++) {
            int en  = s_list[e];
            float w = Wcol[(en & 0xFFFF) * NN];
            if (en & 0x10000) { if (e & 1) aB1 += w; else aB0 += w; }
            else              { if (e & 1) aA1 += w; else aA0 += w; }
        }
        float inA = aA0 + aA1;
        float inB = aB0 + aB1;

        // -------- neuron update --------------------------------------------
        x0 = AR0 * x0 + inA;
        x1 = AR1 * x1 + inA;
        x2 = AR0 * x2 + inB;
        g0 = AD0 * g0 + x0;
        g1 = AD1 * g1 + x1;
        g2 = AD2 * g2 + x2;
        xF = AR0 * xF + inF;
        gF = AD0 * gF + xF;

        float gtot = g0 + 0.5f * g1 + g2 + gF;
        float gE   = -70.0f * g2;
        float Isyn = gE - gtot * U;
        float Un   = U + leak * (10.0f * (-65.0f - U) + Isyn);
        if (ref > 0.0f) Un = -65.0f;             // refractory clamp
        ref = fmaxf(ref - 1.0f, 0.0f);
        float s = ((Un + 50.0f) >= 0.0f) ? 1.0f : 0.0f;
        if (s > 0.0f) { Un = -65.0f; ref = refstep; }
        U = Un;

        // outputs: spikes then volts, both (B,T,N)
        size_t o = ((size_t)b * TT + t) * NN + n;
        out[o]        = s;
        out[VOFF + o] = Un;

        // -------- ballot-ordered spike compaction into my segment ----------
        unsigned m = __ballot_sync(0xFFFFFFFFu, s > 0.0f);
        if (lane == 0) s_wcnt[wid] = __popc(m);
        __syncthreads();                         // (A) wcnt visible
        int base = 0, tot = 0;
#pragma unroll
        for (int w2 = 0; w2 < NWARP; w2++) {
            int v = s_wcnt[w2];
            if (w2 < wid) base += v;
            tot += v;
        }
        if (s > 0.0f)
            d_seg[b][par][rank][base + __popc(m & ((1u << lane) - 1u))] =
                n | (c << 16);
        __threadfence();                         // publish segment entries
        __syncthreads();                         // (B) all entries written

        // -------- per-batch 4-CTA barrier -----------------------------------
        if (tid == 0) {
            d_segcnt[b][par][rank] = tot;
            __threadfence();
            atomicAdd(&d_bar[b], 1u);
            unsigned tgt = (unsigned)(t + 1) * GC;
            while (__ldcg(&d_bar[b]) < tgt) { __nanosleep(32); }
            __threadfence();
        }
        __syncthreads();                         // (C) barrier done

        // -------- combine the 4 segments into s_list (rank-ordered) --------
        int cs[GC];
#pragma unroll
        for (int r = 0; r < GC; r++) cs[r] = __ldcg(&d_segcnt[b][par][r]);
        int offr[GC];
        offr[0] = 0;
#pragma unroll
        for (int r = 1; r < GC; r++) offr[r] = offr[r - 1] + cs[r - 1];
        cnt = offr[GC - 1] + cs[GC - 1];

        {
            int r      = wid & (GC - 1);     // 12 warps -> 4 ranks x 3 stripes
            int stripe = wid >> 2;
            const int* __restrict__ src = d_seg[b][par][r];
            for (int e = stripe * 32 + lane; e < cs[r]; e += 96)
                s_list[offr[r] + e] = __ldcg(&src[e]);
        }
        __syncthreads();                         // (D) s_list ready
    }
}

// ------------------------- launcher -----------------------------------------
extern "C" void kernel_launch(void* const* d_in, const int* in_sizes, int n_in,
                              void* d_out, int out_size) {
    const float* input_spikes = (const float*)d_in[0]; // (B,T,NI)
    const float* weights      = (const float*)d_in[1]; // (NN,NN)
    const float* weights_FF   = (const float*)d_in[2]; // (NI,NN)
    const float* sf           = (const float*)d_in[3]; // (2,2)
    const float* sff          = (const float*)d_in[4]; // (1,2)
    const int*   ct           = (const int*)d_in[5];   // (NN,)
    (void)in_sizes; (void)n_in; (void)out_size;

    init_k<<<1, 64>>>();
    int total = NN * NN + NI * NN;
    scale_k<<<(total + 255) / 256, 256>>>(weights, weights_FF, sf, sff, ct);
    ffl_k<<<BB * TT, 32>>>(input_spikes);
    ffpre_k<<<dim3(NN / 32, BB), FTPB>>>();
    sim_k<<<BB * GC, TPB2>>>(ct, (float*)d_out);
}

// round 3
// speedup vs baseline: 2.4148x; 2.1097x over previous
#include <cuda_runtime.h>
#include <cstdint>

// Problem constants (fixed by the reference)
#define BB 32
#define TT 256
#define NN 1536
#define NI 768

// Sim config: 4-CTA cluster per batch, 384 threads/CTA, 1 neuron/thread.
#define GC    4
#define TPB   384
#define NWARP (TPB / 32)
#define SEG   384                 // per-CTA segment capacity (== TPB)

// exp constants, correctly rounded fp32
#define AR0 0.13533528323661270f   // exp(-2)    : rise tau 0.5 (syn0, syn2, FF)
#define AR1 0.60653065971263342f   // exp(-0.5)  : rise tau 2   (syn1)
#define AD0 0.60653065971263342f   // exp(-0.5)  : decay tau 2  (syn0, FF)
#define AD1 0.99004983374916805f   // exp(-0.01) : decay tau 100(syn1)
#define AD2 0.81873075307798186f   // exp(-0.2)  : decay tau 5  (syn2)

// ------------------------- device scratch (statics; no allocs) -------------
__device__ float d_Wsc[NN * NN];             // weights * sf[ct[n]][ct[m]]
__device__ float d_WFsc[NI * NN];            // weights_FF * sfF[ct[m]]
__device__ float d_IF[(size_t)BB * TT * NN]; // precomputed FF drive
__device__ int   d_ffcnt[BB * TT];           // input spike counts per (b,t)
__device__ int   d_fflist[BB * TT][NI];      // byte offsets j*NN*4

// ------------------------- PTX helpers --------------------------------------
__device__ __forceinline__ uint32_t smem_u32(const void* p) {
    uint32_t a;
    asm("{ .reg .u64 t; cvta.to.shared.u64 t, %1; cvt.u32.u64 %0, t; }"
        : "=r"(a) : "l"(p));
    return a;
}
__device__ __forceinline__ void st_cluster(uint32_t laddr, uint32_t rank, int v) {
    uint32_t ra;
    asm("mapa.shared::cluster.u32 %0, %1, %2;" : "=r"(ra) : "r"(laddr), "r"(rank));
    asm volatile("st.shared::cluster.b32 [%0], %1;" :: "r"(ra), "r"(v) : "memory");
}
#define CLUSTER_SYNC() do { \
    asm volatile("barrier.cluster.arrive.aligned;" ::: "memory"); \
    asm volatile("barrier.cluster.wait.aligned;"   ::: "memory"); \
} while (0)

// ------------------------- weight scaling ----------------------------------
__global__ void scale_k(const float* __restrict__ w, const float* __restrict__ wff,
                        const float* __restrict__ sf, const float* __restrict__ sff,
                        const int* __restrict__ ct) {
    int idx = blockIdx.x * 256 + threadIdx.x;
    if (idx < NN * NN) {
        int n = idx / NN, m = idx % NN;
        d_Wsc[idx] = w[idx] * sf[ct[n] * 2 + ct[m]];
    } else {
        int r = idx - NN * NN;
        if (r < NI * NN) {
            int m = r % NN;
            d_WFsc[r] = wff[r] * sff[ct[m]];   // ct_FF is all zeros -> row 0
        }
    }
}

// ------------------------- FF spike lists (ballot-ordered, byte offsets) ---
__global__ void ffl_k(const float* __restrict__ inp) {
    int bt = blockIdx.x;                      // bt = b*TT + t
    int lane = threadIdx.x;
    const float* row = inp + (size_t)bt * NI;
    int cnt = 0;
    for (int base = 0; base < NI; base += 32) {
        float v = row[base + lane];
        unsigned m = __ballot_sync(0xFFFFFFFFu, v > 0.5f);
        if (v > 0.5f) {
            int p = cnt + __popc(m & ((1u << lane) - 1u));
            d_fflist[bt][p] = (base + lane) * NN * 4;   // byte offset of row
        }
        cnt += __popc(m);
    }
    if (lane == 0) d_ffcnt[bt] = cnt;
}

// ------------------------- FF drive precompute (v2) --------------------------
// CTA = (64-col tile, batch): slab 768x64 fp32 = 196KB stays L1-resident.
// 16 warps, each warp owns 16 timesteps; lanes cover 2 cols each (float2).
#define FCOLS 64
#define FTPB  512
__global__ void __launch_bounds__(FTPB, 2) ffpre_k() {
    int b  = blockIdx.y;
    int c0 = blockIdx.x * FCOLS;
    int w    = threadIdx.x >> 5;
    int lane = threadIdx.x & 31;
    const char* __restrict__ Wc =
        (const char*)d_WFsc + (size_t)(c0 + lane * 2) * 4;
#pragma unroll
    for (int ti = 0; ti < TT / 16; ti++) {
        int t  = w * 16 + ti;
        int bt = b * TT + t;
        int fc = d_ffcnt[bt];
        const int* __restrict__ lst = d_fflist[bt];
        float a0 = 0.f, a1 = 0.f, a2 = 0.f, a3 = 0.f;
        int e = 0;
#pragma unroll 4
        for (; e + 1 < fc; e += 2) {
            int o0 = lst[e], o1 = lst[e + 1];
            float2 v0 = *(const float2*)(Wc + o0);
            float2 v1 = *(const float2*)(Wc + o1);
            a0 += v0.x; a1 += v0.y; a2 += v1.x; a3 += v1.y;
        }
        if (e < fc) {
            float2 v = *(const float2*)(Wc + lst[e]);
            a0 += v.x; a1 += v.y;
        }
        *(float2*)&d_IF[(size_t)bt * NN + c0 + lane * 2] =
            make_float2(a0 + a2, a1 + a3);
    }
}

// ------------------------- main persistent simulator ------------------------
__global__ void __launch_bounds__(TPB, 1) __cluster_dims__(GC, 1, 1)
sim_k(const int* __restrict__ ct, float* __restrict__ out) {
    const int b    = blockIdx.x >> 2;
    const int rank = blockIdx.x & 3;
    const int tid  = threadIdx.x;
    const int wid  = tid >> 5, lane = tid & 31;
    const int n    = rank * TPB + tid;

    // double-buffered type-split spike lists (byte offsets) + counts
    __shared__ int sA[2][NN];
    __shared__ int sB[2][NN];
    __shared__ int sCA[2][GC], sCB[2][GC];
    __shared__ int swA[NWARP], swB[NWARP];

    if (tid < GC) {
        sCA[0][tid] = 0; sCA[1][tid] = 0;
        sCB[0][tid] = 0; sCB[1][tid] = 0;
    }
    __syncthreads();
    CLUSTER_SYNC();                            // peers' counts zeroed

    const int   c       = ct[n];
    const float leak    = c ? 0.01f : 0.005f;  // DT/(tau_mem*g_l)
    const float refstep = c ? 1.0f : 2.0f;     // tau_ref/DT
    const int   entry   = n * NN * 4;          // byte offset of my W row

    float U = -65.0f, x0 = 0, x1 = 0, x2 = 0, g0 = 0, g1 = 0, g2 = 0,
          xF = 0, gF = 0, ref = 0;

    const char* __restrict__ wb = (const char*)d_Wsc + (size_t)n * 4;
    const float* __restrict__ ifp = d_IF + (size_t)b * TT * NN + n;
    const size_t VOFF = (size_t)BB * TT * NN;
    const unsigned lt = (1u << lane) - 1u;

    for (int t = 0; t < TT; t++) {
        const int wp = t & 1, rp = wp ^ 1;

        float inF = __ldcg(ifp + (size_t)t * NN);

        // -------- sparse recurrent gather: two type-split lists -------------
        float aA0 = 0.f, aA1 = 0.f, aA2 = 0.f, aA3 = 0.f;
#pragma unroll
        for (int r = 0; r < GC; r++) {
            int cc = sCA[rp][r];
            const int* seg = &sA[rp][r * SEG];
            int e = 0;
#pragma unroll 2
            for (; e + 3 < cc; e += 4) {
                float w0 = __ldcg((const float*)(wb + seg[e]));
                float w1 = __ldcg((const float*)(wb + seg[e + 1]));
                float w2 = __ldcg((const float*)(wb + seg[e + 2]));
                float w3 = __ldcg((const float*)(wb + seg[e + 3]));
                aA0 += w0; aA1 += w1; aA2 += w2; aA3 += w3;
            }
            for (; e < cc; e++) aA0 += __ldcg((const float*)(wb + seg[e]));
        }
        float aB0 = 0.f, aB1 = 0.f, aB2 = 0.f, aB3 = 0.f;
#pragma unroll
        for (int r = 0; r < GC; r++) {
            int cc = sCB[rp][r];
            const int* seg = &sB[rp][r * SEG];
            int e = 0;
#pragma unroll 2
            for (; e + 3 < cc; e += 4) {
                float w0 = __ldcg((const float*)(wb + seg[e]));
                float w1 = __ldcg((const float*)(wb + seg[e + 1]));
                float w2 = __ldcg((const float*)(wb + seg[e + 2]));
                float w3 = __ldcg((const float*)(wb + seg[e + 3]));
                aB0 += w0; aB1 += w1; aB2 += w2; aB3 += w3;
            }
            for (; e < cc; e++) aB0 += __ldcg((const float*)(wb + seg[e]));
        }
        float inA = (aA0 + aA1) + (aA2 + aA3);
        float inB = (aB0 + aB1) + (aB2 + aB3);

        // -------- neuron update --------------------------------------------
        x0 = AR0 * x0 + inA;
        x1 = AR1 * x1 + inA;
        x2 = AR0 * x2 + inB;
        g0 = AD0 * g0 + x0;
        g1 = AD1 * g1 + x1;
        g2 = AD2 * g2 + x2;
        xF = AR0 * xF + inF;
        gF = AD0 * gF + xF;

        float gtot = g0 + 0.5f * g1 + g2 + gF;
        float gE   = -70.0f * g2;
        float Isyn = gE - gtot * U;
        float Un   = U + leak * (10.0f * (-65.0f - U) + Isyn);
        if (ref > 0.0f) Un = -65.0f;             // refractory clamp
        ref = fmaxf(ref - 1.0f, 0.0f);
        float s = ((Un + 50.0f) >= 0.0f) ? 1.0f : 0.0f;
        bool spk = (s > 0.0f);
        if (spk) { Un = -65.0f; ref = refstep; }
        U = Un;

        // outputs: spikes then volts, both (B,T,N)
        size_t o = ((size_t)b * TT + t) * NN + n;
        out[o]        = s;
        out[VOFF + o] = Un;

        // -------- ballot-ordered compaction, pushed to all 4 CTAs ----------
        unsigned mA = __ballot_sync(0xFFFFFFFFu, spk && (c == 0));
        unsigned mB = __ballot_sync(0xFFFFFFFFu, spk && (c != 0));
        if (lane == 0) { swA[wid] = __popc(mA); swB[wid] = __popc(mB); }
        __syncthreads();                          // also: everyone done gathering
        int baseA = 0, totA = 0, baseB = 0, totB = 0;
#pragma unroll
        for (int w2 = 0; w2 < NWARP; w2++) {
            int vA = swA[w2], vB = swB[w2];
            if (w2 < wid) { baseA += vA; baseB += vB; }
            totA += vA; totB += vB;
        }
        if (spk) {
            uint32_t la;
            if (c == 0) {
                int pos = rank * SEG + baseA + __popc(mA & lt);
                la = smem_u32(&sA[wp][pos]);
            } else {
                int pos = rank * SEG + baseB + __popc(mB & lt);
                la = smem_u32(&sB[wp][pos]);
            }
#pragma unroll
            for (int r = 0; r < GC; r++) st_cluster(la, r, entry);
        }
        if (tid == 0) {
            uint32_t laA = smem_u32(&sCA[wp][rank]);
            uint32_t laB = smem_u32(&sCB[wp][rank]);
#pragma unroll
            for (int r = 0; r < GC; r++) {
                st_cluster(laA, r, totA);
                st_cluster(laB, r, totB);
            }
        }
        // one cluster barrier per step: arrive=release, wait=acquire for the
        // shared::cluster stores above; doubles as the local barrier.
        CLUSTER_SYNC();
    }
}

// ------------------------- launcher -----------------------------------------
extern "C" void kernel_launch(void* const* d_in, const int* in_sizes, int n_in,
                              void* d_out, int out_size) {
    const float* input_spikes = (const float*)d_in[0]; // (B,T,NI)
    const float* weights      = (const float*)d_in[1]; // (NN,NN)
    const float* weights_FF   = (const float*)d_in[2]; // (NI,NN)
    const float* sf           = (const float*)d_in[3]; // (2,2)
    const float* sff          = (const float*)d_in[4]; // (1,2)
    const int*   ct           = (const int*)d_in[5];   // (NN,)
    (void)in_sizes; (void)n_in; (void)out_size;

    int total = NN * NN + NI * NN;
    scale_k<<<(total + 255) / 256, 256>>>(weights, weights_FF, sf, sff, ct);
    ffl_k<<<BB * TT, 32>>>(input_spikes);
    ffpre_k<<<dim3(NN / FCOLS, BB), FTPB>>>();
    sim_k<<<BB * GC, TPB>>>(ct, (float*)d_out);
}